// round 12
// baseline (speedup 1.0000x reference)
#include <cuda_runtime.h>
#include <cuda_bf16.h>
#include <math.h>
#include <stdint.h>

#define M_BOXES 512
#define C_FEAT  512
#define POOLSZ  14
#define SP      196
#define HID     1024
#define NCLS    81
#define OCONV   256
#define KFC     100352
#define SPLITK  8
#define KSLICE  (KFC/SPLITK)
#define PART    (M_BOXES*NCLS)
#define MROWS   (M_BOXES*SP)

// smem tile geometry: 128 rows x 8 chunks(16B) data + 1 pad chunk = 144B pitch
#define PITCH   144
#define OPBYTES (128*PITCH)      // 18432 per operand
#define STAGEB  (2*OPBYTES)      // 36864 per stage (A+B)
#define NSTAGE  3

__device__ __nv_bfloat16 g_pA_hi[(size_t)MROWS*C_FEAT];
__device__ __nv_bfloat16 g_pA_lo[(size_t)MROWS*C_FEAT];
__device__ __nv_bfloat16 g_wfc_hi[(size_t)HID*KFC];
__device__ __nv_bfloat16 g_wfc_lo[(size_t)HID*KFC];
__device__ __nv_bfloat16 g_wcv_hi[(size_t)9*OCONV*C_FEAT];
__device__ __nv_bfloat16 g_wcv_lo[(size_t)9*OCONV*C_FEAT];
__device__ float         g_partial[(size_t)SPLITK*M_BOXES*HID];
__device__ float         g_h[M_BOXES*HID];
__device__ float         g_zsum[M_BOXES*OCONV];
__device__ float         g_boxp[M_BOXES*8];

__device__ __forceinline__ uint32_t smem_u32(const void* p){
    uint32_t a; asm("{ .reg .u64 t; cvta.to.shared.u64 t, %1; cvt.u32.u64 %0, t; }":"=r"(a):"l"(p)); return a;
}
__device__ __forceinline__ void cp16(uint32_t dst, const void* src){
    asm volatile("cp.async.ca.shared.global [%0], [%1], 16;"::"r"(dst),"l"(src));
}
__device__ __forceinline__ void cp16z(uint32_t dst, const void* src, int sz){
    asm volatile("cp.async.ca.shared.global [%0], [%1], 16, %2;"::"r"(dst),"l"(src),"r"(sz));
}
__device__ __forceinline__ void cp_commit(){ asm volatile("cp.async.commit_group;":::"memory"); }
template<int N> __device__ __forceinline__ void cp_wait(){
    asm volatile("cp.async.wait_group %0;"::"n"(N):"memory");
}
__device__ __forceinline__ void ldm4(uint32_t* f, uint32_t addr){
    asm volatile("ldmatrix.sync.aligned.m8n8.x4.shared.b16 {%0,%1,%2,%3}, [%4];"
        :"=r"(f[0]),"=r"(f[1]),"=r"(f[2]),"=r"(f[3]):"r"(addr));
}
__device__ __forceinline__ void mma16816(float* c, const uint32_t* a, const uint32_t* b){
    asm volatile("mma.sync.aligned.m16n8k16.row.col.f32.bf16.bf16.f32 "
        "{%0,%1,%2,%3},{%4,%5,%6,%7},{%8,%9},{%0,%1,%2,%3};"
        :"+f"(c[0]),"+f"(c[1]),"+f"(c[2]),"+f"(c[3])
        :"r"(a[0]),"r"(a[1]),"r"(a[2]),"r"(a[3]),"r"(b[0]),"r"(b[1]));
}

// 3-pass HMMA (hh, lh, hl) with fragment reuse: A-hi and B-hi loaded once.
__device__ __forceinline__ void hmma_tile(uint32_t aAddr, uint32_t bAddr, float acc[16][4]){
    #pragma unroll
    for (int s=0; s<2; s++){
        uint32_t ah[2][4], al[2][4], bfr[4][4];
        // hi fragments
        ldm4(ah[0], aAddr + s*32);
        ldm4(ah[1], aAddr + 16*PITCH + s*32);
        #pragma unroll
        for (int p=0;p<4;p++) ldm4(bfr[p], bAddr + p*16*PITCH + s*32);
        // pass hh
        #pragma unroll
        for (int mi=0;mi<2;mi++)
            #pragma unroll
            for (int ni=0;ni<8;ni++)
                mma16816(acc[mi*8+ni], ah[mi], &bfr[ni>>1][(ni&1)*2]);
        // pass lh: A-lo x B-hi (B-hi still live)
        ldm4(al[0], aAddr + 64 + s*32);
        ldm4(al[1], aAddr + 16*PITCH + 64 + s*32);
        #pragma unroll
        for (int mi=0;mi<2;mi++)
            #pragma unroll
            for (int ni=0;ni<8;ni++)
                mma16816(acc[mi*8+ni], al[mi], &bfr[ni>>1][(ni&1)*2]);
        // pass hl: A-hi x B-lo (overwrite B regs)
        #pragma unroll
        for (int p=0;p<4;p++) ldm4(bfr[p], bAddr + p*16*PITCH + 64 + s*32);
        #pragma unroll
        for (int mi=0;mi<2;mi++)
            #pragma unroll
            for (int ni=0;ni<8;ni++)
                mma16816(acc[mi*8+ni], ah[mi], &bfr[ni>>1][(ni&1)*2]);
    }
}

__global__ void k_prep(const float* __restrict__ boxes, const int* __restrict__ bidx,
                       const int* __restrict__ ph, const int* __restrict__ pw){
    int m = threadIdx.x; if (m >= M_BOXES) return;
    int ih = ph[0], iw = pw[0];
    if (ih <= 0 || ih > 100000) ih = (int)__int_as_float(ph[0]);
    if (iw <= 0 || iw > 100000) iw = (int)__int_as_float(pw[0]);
    float alpha = (224.0f/800.0f)*(float)min(ih,iw);
    float x1=boxes[m*4+0], y1=boxes[m*4+1], x2=boxes[m*4+2], y2=boxes[m*4+3];
    float s = sqrtf(fmaxf(fabsf(x2-x1)*fabsf(y2-y1), 1e-6f));
    float k = floorf(4.0f + log2f(s/alpha));
    int lvl = (int)fminf(fmaxf(k-2.0f,0.0f),3.0f);
    float sc = 1.0f/(float)(4<<lvl);
    g_boxp[m*8+0]=x1*sc; g_boxp[m*8+1]=y1*sc; g_boxp[m*8+2]=x2*sc; g_boxp[m*8+3]=y2*sc;
    g_boxp[m*8+4]=(float)lvl; g_boxp[m*8+5]=(float)bidx[m];
}

// fused RoIAlign + transpose + bf16 hi/lo split: block = (box m, 64-channel tile)
__global__ void __launch_bounds__(256) k_roi2(const float* __restrict__ p2, const float* __restrict__ p3,
                                              const float* __restrict__ p4, const float* __restrict__ p5){
    __shared__ float s[64][201];
    int m = blockIdx.x, c0 = blockIdx.y*64;
    const float* bp = &g_boxp[m*8];
    int lvl = (int)bp[4], bi = (int)bp[5];
    const float* feat = (lvl==0)?p2:(lvl==1)?p3:(lvl==2)?p4:p5;
    int H = 200>>lvl, W = H;
    float sx1 = bp[0], sy1 = bp[1], sx2 = bp[2], sy2 = bp[3];
    int tid = threadIdx.x;
    int cl = tid>>5, sps = tid&31;      // cl: 0..7, sps: 0..31

    #pragma unroll
    for (int spc=0; spc<7; spc++){
        int sp = spc*32 + sps;
        if (sp < SP){
            int py = sp/POOLSZ, px = sp - py*POOLSZ;
            float xs = sx1 + (px+0.5f)/POOLSZ*(sx2-sx1);
            float ys = sy1 + (py+0.5f)/POOLSZ*(sy2-sy1);
            float x0f = floorf(xs), y0f = floorf(ys);
            float lx = xs-x0f, ly = ys-y0f;
            int ix0 = min(max((int)x0f,0),W-1), ix1 = min(max((int)x0f+1,0),W-1);
            int iy0 = min(max((int)y0f,0),H-1), iy1 = min(max((int)y0f+1,0),H-1);
            float w00 = (1.f-ly)*(1.f-lx), w01 = (1.f-ly)*lx, w10 = ly*(1.f-lx), w11 = ly*lx;
            int o00 = iy0*W+ix0, o01 = iy0*W+ix1, o10 = iy1*W+ix0, o11 = iy1*W+ix1;
            #pragma unroll
            for (int ci=0; ci<8; ci++){
                int c = c0 + cl*8 + ci;
                const float* base = feat + ((size_t)(bi*C_FEAT + c))*(size_t)(H*W);
                s[cl*8+ci][sp] = base[o00]*w00 + base[o01]*w01 + base[o10]*w10 + base[o11]*w11;
            }
        }
    }
    __syncthreads();
    int cl2 = tid&63, sp2 = tid>>6;     // cl2: 0..63, sp2: 0..3
    #pragma unroll 7
    for (int j=0;j<49;j++){
        int sp = sp2 + j*4;
        float v = s[cl2][sp];
        __nv_bfloat16 h = __float2bfloat16(v);
        size_t o = ((size_t)m*SP+sp)*C_FEAT + c0 + cl2;
        g_pA_hi[o]=h; g_pA_lo[o]=__float2bfloat16(v-__bfloat162float(h));
    }
}

// w_fc1 [c*196+sp][n] -> [n][sp*512+c] hi/lo
__global__ void __launch_bounds__(256) k_wfct(const float* __restrict__ w){
    __shared__ float s[32][33];
    int sp = blockIdx.z, c0 = blockIdx.y*32, n0 = blockIdx.x*32;
    int tx = threadIdx.x, ty = threadIdx.y;
    #pragma unroll
    for (int i=0;i<4;i++){
        int cl = ty+i*8;
        s[cl][tx] = w[((size_t)(c0+cl)*SP+sp)*HID + n0+tx];
    }
    __syncthreads();
    #pragma unroll
    for (int i=0;i<4;i++){
        int nl = ty+i*8;
        float v = s[tx][nl];
        __nv_bfloat16 h = __float2bfloat16(v);
        size_t o = (size_t)(n0+nl)*KFC + (size_t)sp*C_FEAT + c0+tx;
        g_wfc_hi[o]=h; g_wfc_lo[o]=__float2bfloat16(v-__bfloat162float(h));
    }
}

// w_conv OIHW -> [r][oc][ic] hi/lo
__global__ void k_wcvt(const float* __restrict__ w){
    int idx = blockIdx.x*blockDim.x + threadIdx.x;
    if (idx >= 9*OCONV*C_FEAT) return;
    int r = idx/(OCONV*C_FEAT), rm = idx%(OCONV*C_FEAT);
    int oc = rm/C_FEAT, ic = rm%C_FEAT;
    float v = w[(size_t)oc*4608 + ic*9 + r];
    __nv_bfloat16 h = __float2bfloat16(v);
    g_wcv_hi[idx]=h; g_wcv_lo[idx]=__float2bfloat16(v-__bfloat162float(h));
}

__global__ void k_zero(){
    int i = blockIdx.x*blockDim.x + threadIdx.x;
    if (i < M_BOXES*OCONV) g_zsum[i]=0.f;
}

// ---------------- FC1 HMMA GEMM: grid (8 n, 4 m, 8 splitK), 3-stage ring ----------------
__global__ void __launch_bounds__(256,2) k_mm1(){
    extern __shared__ __align__(16) char dynsm[];
    uint32_t sbase = smem_u32(dynsm);
    int tid = threadIdx.x, wid = tid>>5, L = tid&31;
    int widm = wid&3, widn = wid>>2;
    int bn = blockIdx.x, bm = blockIdx.y, sk = blockIdx.z;
    int rw = tid>>1, t1 = tid&1;
    int k0b = sk*KSLICE;
    const int nIter = KSLICE/32;   // 392

    const __nv_bfloat16* Asrc = (t1 ? g_pA_lo  : g_pA_hi)  + (size_t)(bm*128+rw)*KFC;
    const __nv_bfloat16* Bsrc = (t1 ? g_wfc_lo : g_wfc_hi) + (size_t)(bn*128+rw)*KFC;
    uint32_t ld_a = sbase + rw*PITCH + t1*64;
    uint32_t ld_b = ld_a + OPBYTES;

    uint32_t aA = sbase + (widm*32 + (L&7) + 8*((L>>3)&1))*PITCH + (L>>4)*16;
    uint32_t aB = sbase + OPBYTES + (widn*64 + (L&7) + 8*(L>>4))*PITCH + ((L>>3)&1)*16;

    float acc[16][4];
    #pragma unroll
    for (int i=0;i<16;i++){ acc[i][0]=0.f; acc[i][1]=0.f; acc[i][2]=0.f; acc[i][3]=0.f; }

#define FC_LD(ST,IT) do { \
        int kb_ = k0b + (IT)*32; \
        uint32_t off_ = (uint32_t)(ST)*STAGEB; \
        _Pragma("unroll") \
        for (int j=0;j<4;j++) cp16(ld_a + off_ + j*16, Asrc + kb_ + j*8); \
        _Pragma("unroll") \
        for (int j=0;j<4;j++) cp16(ld_b + off_ + j*16, Bsrc + kb_ + j*8); \
        cp_commit(); } while(0)

    FC_LD(0,0);
    FC_LD(1,1);
    int st = 0;
    for (int it=0; it<nIter; ++it){
        if (it+1 < nIter) cp_wait<1>(); else cp_wait<0>();
        __syncthreads();
        if (it+2 < nIter){
            int s2 = st+2; if (s2>=NSTAGE) s2-=NSTAGE;
            FC_LD(s2, it+2);
        }
        uint32_t off = (uint32_t)st*STAGEB;
        hmma_tile(aA + off, aB + off, acc);
        if (++st == NSTAGE) st = 0;
    }
#undef FC_LD

    #pragma unroll
    for (int mi=0;mi<2;mi++)
        #pragma unroll
        for (int ni=0;ni<8;ni++)
            #pragma unroll
            for (int cq=0;cq<4;cq++){
                int row = bm*128 + widm*32 + mi*16 + (L>>2) + 8*(cq>>1);
                int col = bn*128 + widn*64 + ni*8 + 2*(L&3) + (cq&1);
                g_partial[((size_t)sk*M_BOXES + row)*HID + col] = acc[mi*8+ni][cq];
            }
}

__global__ void k_reduce1(const float* __restrict__ bfc1){
    int idx = blockIdx.x*blockDim.x + threadIdx.x;
    if (idx >= M_BOXES*HID) return;
    float v = 0.f;
    #pragma unroll
    for (int s=0;s<SPLITK;s++) v += g_partial[(size_t)s*M_BOXES*HID + idx];
    g_h[idx] = fmaxf(v + bfc1[idx%HID], 0.f);
}

__global__ void __launch_bounds__(128) k_heads(const float* __restrict__ wc, const float* __restrict__ bc,
                                               const float* __restrict__ wb, const float* __restrict__ bb,
                                               float* __restrict__ out){
    __shared__ float hrow[HID];
    __shared__ float lg[NCLS];
    __shared__ float mx, sm;
    int m = blockIdx.x, tid = threadIdx.x;
    for (int k=tid;k<HID;k+=blockDim.x) hrow[k] = g_h[m*HID+k];
    __syncthreads();
    if (tid<NCLS){
        float ac = bc[tid], ab = bb[tid];
        for (int k=0;k<HID;k++){
            float h = hrow[k];
            ac = fmaf(h, wc[k*NCLS+tid], ac);
            ab = fmaf(h, wb[k*NCLS+tid], ab);
        }
        lg[tid]=ac;
        out[PART + m*NCLS + tid] = ab;
    }
    __syncthreads();
    if (tid==0){ float v=-1e30f; for(int c=0;c<NCLS;c++) v=fmaxf(v,lg[c]); mx=v; }
    __syncthreads();
    if (tid<NCLS) lg[tid] = expf(lg[tid]-mx);
    __syncthreads();
    if (tid==0){ float v=0.f; for(int c=0;c<NCLS;c++) v+=lg[c]; sm=v; }
    __syncthreads();
    if (tid<NCLS) out[m*NCLS+tid] = lg[tid]/sm;
}

// ---------------- conv HMMA: 9 shifted taps in K; grid (2 n, 784 m), 3-stage ring ----------------
__global__ void __launch_bounds__(256,2) k_mm2(const float* __restrict__ bconv){
    extern __shared__ __align__(16) char dynsm[];
    uint32_t sbase = smem_u32(dynsm);
    int tid = threadIdx.x, wid = tid>>5, L = tid&31;
    int widm = wid&3, widn = wid>>2;
    int nbase = blockIdx.x*128;
    int rowbase = blockIdx.y*128;
    int rw = tid>>1, t1 = tid&1;
    const int nIter = 144;  // 9 taps * 16

    int grow = rowbase + rw;
    int am = grow/SP;
    int asp = grow - am*SP;
    int ay = asp/POOLSZ, ax = asp - ay*POOLSZ;
    const __nv_bfloat16* Abase0 = (t1 ? g_pA_lo : g_pA_hi) + (size_t)am*SP*C_FEAT;
    const __nv_bfloat16* Bsrc0  = (t1 ? g_wcv_lo : g_wcv_hi);
    uint32_t ld_a = sbase + rw*PITCH + t1*64;
    uint32_t ld_b = ld_a + OPBYTES;

    uint32_t aA = sbase + (widm*32 + (L&7) + 8*((L>>3)&1))*PITCH + (L>>4)*16;
    uint32_t aB = sbase + OPBYTES + (widn*64 + (L&7) + 8*(L>>4))*PITCH + ((L>>3)&1)*16;

    float acc[16][4];
    #pragma unroll
    for (int i=0;i<16;i++){ acc[i][0]=0.f; acc[i][1]=0.f; acc[i][2]=0.f; acc[i][3]=0.f; }

#define CV_LD(ST,IT) do { \
        int r_ = (IT)>>4, kk_ = ((IT)&15)*32; \
        int dy_ = r_/3 - 1, dx_ = r_ - (r_/3)*3 - 1; \
        int yy_ = ay+dy_, xx_ = ax+dx_; \
        int ok_ = (((unsigned)yy_ < (unsigned)POOLSZ) && ((unsigned)xx_ < (unsigned)POOLSZ)) ? 16 : 0; \
        const __nv_bfloat16* as_ = Abase0 + (size_t)(ok_ ? (yy_*POOLSZ+xx_) : 0)*C_FEAT + kk_; \
        const __nv_bfloat16* bs_ = Bsrc0 + ((size_t)r_*OCONV + nbase + rw)*C_FEAT + kk_; \
        uint32_t off_ = (uint32_t)(ST)*STAGEB; \
        _Pragma("unroll") \
        for (int j=0;j<4;j++) cp16z(ld_a + off_ + j*16, as_ + j*8, ok_); \
        _Pragma("unroll") \
        for (int j=0;j<4;j++) cp16(ld_b + off_ + j*16, bs_ + j*8); \
        cp_commit(); } while(0)

    CV_LD(0,0);
    CV_LD(1,1);
    int st = 0;
    for (int it=0; it<nIter; ++it){
        if (it+1 < nIter) cp_wait<1>(); else cp_wait<0>();
        __syncthreads();
        if (it+2 < nIter){
            int s2 = st+2; if (s2>=NSTAGE) s2-=NSTAGE;
            CV_LD(s2, it+2);
        }
        uint32_t off = (uint32_t)st*STAGEB;
        hmma_tile(aA + off, aB + off, acc);
        if (++st == NSTAGE) st = 0;
    }
#undef CV_LD

    // epilogue: bias+relu, xor-shuffle reduce 8 rows, atomicAdd per box
    #pragma unroll
    for (int mi=0;mi<2;mi++)
        #pragma unroll
        for (int cq2=0;cq2<2;cq2++){
            int rbase = rowbase + widm*32 + mi*16 + 8*cq2;
            int b0 = rbase/SP, b1 = (rbase+7)/SP;
            int mybox = (rbase + (L>>2))/SP;
            #pragma unroll
            for (int ni=0;ni<8;ni++)
                #pragma unroll
                for (int q=0;q<2;q++){
                    int cq = cq2*2 + q;
                    int col = nbase + widn*64 + ni*8 + 2*(L&3) + q;
                    float z = fmaxf(acc[mi*8+ni][cq] + __ldg(&bconv[col]), 0.f);
                    float z0 = (mybox==b0) ? z : 0.f;
                    z0 += __shfl_xor_sync(0xffffffffu, z0, 4);
                    z0 += __shfl_xor_sync(0xffffffffu, z0, 8);
                    z0 += __shfl_xor_sync(0xffffffffu, z0, 16);
                    if ((L>>2)==0) atomicAdd(&g_zsum[b0*OCONV+col], z0);
                    if (b1 != b0){
                        float z1 = (mybox==b1) ? z : 0.f;
                        z1 += __shfl_xor_sync(0xffffffffu, z1, 4);
                        z1 += __shfl_xor_sync(0xffffffffu, z1, 8);
                        z1 += __shfl_xor_sync(0xffffffffu, z1, 16);
                        if ((L>>2)==0) atomicAdd(&g_zsum[b1*OCONV+col], z1);
                    }
                }
        }
}

__global__ void __launch_bounds__(128) k_maskhead(const float* __restrict__ wm,
                                                  const float* __restrict__ bm_,
                                                  float* __restrict__ out){
    int m = blockIdx.x, t = threadIdx.x;
    if (t >= NCLS) return;
    float acc = bm_[t];
    for (int oc=0; oc<OCONV; oc++)
        acc = fmaf(g_zsum[m*OCONV+oc]*(1.0f/196.0f), wm[oc*NCLS+t], acc);
    out[2*PART + m*NCLS + t] = 1.0f/(1.0f + expf(-acc));
}

extern "C" void kernel_launch(void* const* d_in, const int* in_sizes, int n_in,
                              void* d_out, int out_size){
    const float* p2     = (const float*)d_in[0];
    const float* p3     = (const float*)d_in[1];
    const float* p4     = (const float*)d_in[2];
    const float* p5     = (const float*)d_in[3];
    const float* boxes  = (const float*)d_in[4];
    const int*   bidx   = (const int*)  d_in[5];
    const float* w_fc1  = (const float*)d_in[6];
    const float* b_fc1  = (const float*)d_in[7];
    const float* w_cls  = (const float*)d_in[8];
    const float* b_cls  = (const float*)d_in[9];
    const float* w_box  = (const float*)d_in[10];
    const float* b_box  = (const float*)d_in[11];
    const float* w_conv = (const float*)d_in[12];
    const float* b_conv = (const float*)d_in[13];
    const float* w_mfc  = (const float*)d_in[14];
    const float* b_mfc  = (const float*)d_in[15];
    const int*   img_h  = (const int*)  d_in[16];
    const int*   img_w  = (const int*)  d_in[17];
    float* out = (float*)d_out;

    cudaFuncSetAttribute(k_mm1, cudaFuncAttributeMaxDynamicSharedMemorySize, NSTAGE*STAGEB);
    cudaFuncSetAttribute(k_mm2, cudaFuncAttributeMaxDynamicSharedMemorySize, NSTAGE*STAGEB);

    k_prep<<<1, 512>>>(boxes, bidx, img_h, img_w);
    k_wcvt<<<(9*OCONV*C_FEAT + 255)/256, 256>>>(w_conv);
    k_zero<<<(M_BOXES*OCONV + 255)/256, 256>>>();

    k_roi2<<<dim3(M_BOXES, C_FEAT/64), 256>>>(p2, p3, p4, p5);
    k_wfct<<<dim3(32, 16, 196), dim3(32, 8)>>>(w_fc1);

    k_mm1<<<dim3(8, 4, 8), 256, NSTAGE*STAGEB>>>();
    k_reduce1<<<(M_BOXES*HID + 255)/256, 256>>>(b_fc1);
    k_heads<<<M_BOXES, 128>>>(w_cls, b_cls, w_box, b_box, out);

    k_mm2<<<dim3(2, 784), 256, NSTAGE*STAGEB>>>(b_conv);
    k_maskhead<<<M_BOXES, 128>>>(w_mfc, b_mfc, out);
}

// round 14
// speedup vs baseline: 1.2354x; 1.2354x over previous
#include <cuda_runtime.h>
#include <cuda_bf16.h>
#include <math.h>
#include <stdint.h>

#define M_BOXES 512
#define C_FEAT  512
#define POOLSZ  14
#define SP      196
#define HID     1024
#define NCLS    81
#define OCONV   256
#define KFC     100352
#define SPLITK  8
#define KSLICE  (KFC/SPLITK)
#define PART    (M_BOXES*NCLS)
#define MROWS   (M_BOXES*SP)

// smem tile geometry: 128 rows x 8 chunks(16B) data + 1 pad chunk = 144B pitch
#define PITCH   144
#define OPBYTES (128*PITCH)      // 18432 per operand
#define STAGEB  (2*OPBYTES)      // 36864 per stage (A+B)

__device__ __nv_bfloat16 g_pA_hi[(size_t)MROWS*C_FEAT];
__device__ __nv_bfloat16 g_pA_lo[(size_t)MROWS*C_FEAT];
__device__ __nv_bfloat16 g_wfc_hi[(size_t)HID*KFC];
__device__ __nv_bfloat16 g_wfc_lo[(size_t)HID*KFC];
__device__ __nv_bfloat16 g_wcv_hi[(size_t)9*OCONV*C_FEAT];
__device__ __nv_bfloat16 g_wcv_lo[(size_t)9*OCONV*C_FEAT];
__device__ float         g_partial[(size_t)SPLITK*M_BOXES*HID];
__device__ float         g_h[M_BOXES*HID];
__device__ float         g_zsum[M_BOXES*OCONV];
__device__ float         g_boxp[M_BOXES*8];

__device__ __forceinline__ uint32_t smem_u32(const void* p){
    uint32_t a; asm("{ .reg .u64 t; cvta.to.shared.u64 t, %1; cvt.u32.u64 %0, t; }":"=r"(a):"l"(p)); return a;
}
__device__ __forceinline__ void cp16(uint32_t dst, const void* src){
    asm volatile("cp.async.ca.shared.global [%0], [%1], 16;"::"r"(dst),"l"(src));
}
__device__ __forceinline__ void cp16z(uint32_t dst, const void* src, int sz){
    asm volatile("cp.async.ca.shared.global [%0], [%1], 16, %2;"::"r"(dst),"l"(src),"r"(sz));
}
__device__ __forceinline__ void cp_commit(){ asm volatile("cp.async.commit_group;":::"memory"); }
template<int N> __device__ __forceinline__ void cp_wait(){
    asm volatile("cp.async.wait_group %0;"::"n"(N):"memory");
}
__device__ __forceinline__ void ldm4(uint32_t* f, uint32_t addr){
    asm volatile("ldmatrix.sync.aligned.m8n8.x4.shared.b16 {%0,%1,%2,%3}, [%4];"
        :"=r"(f[0]),"=r"(f[1]),"=r"(f[2]),"=r"(f[3]):"r"(addr));
}
__device__ __forceinline__ void mma16816(float* c, const uint32_t* a, const uint32_t* b){
    asm volatile("mma.sync.aligned.m16n8k16.row.col.f32.bf16.bf16.f32 "
        "{%0,%1,%2,%3},{%4,%5,%6,%7},{%8,%9},{%0,%1,%2,%3};"
        :"+f"(c[0]),"+f"(c[1]),"+f"(c[2]),"+f"(c[3])
        :"r"(a[0]),"r"(a[1]),"r"(a[2]),"r"(a[3]),"r"(b[0]),"r"(b[1]));
}

// 3-pass (hh, hl, lh) HMMA over one 128x128x32 stage — R9 proven-fast ordering.
__device__ __forceinline__ void hmma_tile(uint32_t aAddr, uint32_t bAddr, float acc[16][4]){
    #pragma unroll
    for (int pass=0; pass<3; pass++){
        const int ca = (pass==2)?64:0;   // A lo half byte offset
        const int cb = (pass==1)?64:0;   // B lo half
        #pragma unroll
        for (int s=0; s<2; s++){
            uint32_t af[2][4], bf[4][4];
            ldm4(af[0], aAddr + ca + s*32);
            ldm4(af[1], aAddr + 16*PITCH + ca + s*32);
            #pragma unroll
            for (int p=0;p<4;p++) ldm4(bf[p], bAddr + p*16*PITCH + cb + s*32);
            #pragma unroll
            for (int mi=0;mi<2;mi++)
                #pragma unroll
                for (int ni=0;ni<8;ni++)
                    mma16816(acc[mi*8+ni], af[mi], &bf[ni>>1][(ni&1)*2]);
        }
    }
}

__global__ void k_prep(const float* __restrict__ boxes, const int* __restrict__ bidx,
                       const int* __restrict__ ph, const int* __restrict__ pw){
    int m = threadIdx.x; if (m >= M_BOXES) return;
    int ih = ph[0], iw = pw[0];
    if (ih <= 0 || ih > 100000) ih = (int)__int_as_float(ph[0]);
    if (iw <= 0 || iw > 100000) iw = (int)__int_as_float(pw[0]);
    float alpha = (224.0f/800.0f)*(float)min(ih,iw);
    float x1=boxes[m*4+0], y1=boxes[m*4+1], x2=boxes[m*4+2], y2=boxes[m*4+3];
    float s = sqrtf(fmaxf(fabsf(x2-x1)*fabsf(y2-y1), 1e-6f));
    float k = floorf(4.0f + log2f(s/alpha));
    int lvl = (int)fminf(fmaxf(k-2.0f,0.0f),3.0f);
    float sc = 1.0f/(float)(4<<lvl);
    g_boxp[m*8+0]=x1*sc; g_boxp[m*8+1]=y1*sc; g_boxp[m*8+2]=x2*sc; g_boxp[m*8+3]=y2*sc;
    g_boxp[m*8+4]=(float)lvl; g_boxp[m*8+5]=(float)bidx[m];
}

// fused RoIAlign + transpose + bf16 hi/lo split: block = (box m, 64-channel tile)
__global__ void __launch_bounds__(256) k_roi2(const float* __restrict__ p2, const float* __restrict__ p3,
                                              const float* __restrict__ p4, const float* __restrict__ p5){
    __shared__ float s[64][201];
    int m = blockIdx.x, c0 = blockIdx.y*64;
    const float* bp = &g_boxp[m*8];
    int lvl = (int)bp[4], bi = (int)bp[5];
    const float* feat = (lvl==0)?p2:(lvl==1)?p3:(lvl==2)?p4:p5;
    int H = 200>>lvl, W = H;
    float sx1 = bp[0], sy1 = bp[1], sx2 = bp[2], sy2 = bp[3];
    int tid = threadIdx.x;
    int cl = tid>>5, sps = tid&31;

    #pragma unroll
    for (int spc=0; spc<7; spc++){
        int sp = spc*32 + sps;
        if (sp < SP){
            int py = sp/POOLSZ, px = sp - py*POOLSZ;
            float xs = sx1 + (px+0.5f)/POOLSZ*(sx2-sx1);
            float ys = sy1 + (py+0.5f)/POOLSZ*(sy2-sy1);
            float x0f = floorf(xs), y0f = floorf(ys);
            float lx = xs-x0f, ly = ys-y0f;
            int ix0 = min(max((int)x0f,0),W-1), ix1 = min(max((int)x0f+1,0),W-1);
            int iy0 = min(max((int)y0f,0),H-1), iy1 = min(max((int)y0f+1,0),H-1);
            float w00 = (1.f-ly)*(1.f-lx), w01 = (1.f-ly)*lx, w10 = ly*(1.f-lx), w11 = ly*lx;
            int o00 = iy0*W+ix0, o01 = iy0*W+ix1, o10 = iy1*W+ix0, o11 = iy1*W+ix1;
            #pragma unroll
            for (int ci=0; ci<8; ci++){
                int c = c0 + cl*8 + ci;
                const float* base = feat + ((size_t)(bi*C_FEAT + c))*(size_t)(H*W);
                s[cl*8+ci][sp] = base[o00]*w00 + base[o01]*w01 + base[o10]*w10 + base[o11]*w11;
            }
        }
    }
    __syncthreads();
    int cl2 = tid&63, sp2 = tid>>6;
    #pragma unroll 7
    for (int j=0;j<49;j++){
        int sp = sp2 + j*4;
        float v = s[cl2][sp];
        __nv_bfloat16 h = __float2bfloat16(v);
        size_t o = ((size_t)m*SP+sp)*C_FEAT + c0 + cl2;
        g_pA_hi[o]=h; g_pA_lo[o]=__float2bfloat16(v-__bfloat162float(h));
    }
}

// w_fc1 [c*196+sp][n] -> [n][sp*512+c] hi/lo
__global__ void __launch_bounds__(256) k_wfct(const float* __restrict__ w){
    __shared__ float s[32][33];
    int sp = blockIdx.z, c0 = blockIdx.y*32, n0 = blockIdx.x*32;
    int tx = threadIdx.x, ty = threadIdx.y;
    #pragma unroll
    for (int i=0;i<4;i++){
        int cl = ty+i*8;
        s[cl][tx] = w[((size_t)(c0+cl)*SP+sp)*HID + n0+tx];
    }
    __syncthreads();
    #pragma unroll
    for (int i=0;i<4;i++){
        int nl = ty+i*8;
        float v = s[tx][nl];
        __nv_bfloat16 h = __float2bfloat16(v);
        size_t o = (size_t)(n0+nl)*KFC + (size_t)sp*C_FEAT + c0+tx;
        g_wfc_hi[o]=h; g_wfc_lo[o]=__float2bfloat16(v-__bfloat162float(h));
    }
}

// w_conv OIHW -> [r][oc][ic] hi/lo
__global__ void k_wcvt(const float* __restrict__ w){
    int idx = blockIdx.x*blockDim.x + threadIdx.x;
    if (idx >= 9*OCONV*C_FEAT) return;
    int r = idx/(OCONV*C_FEAT), rm = idx%(OCONV*C_FEAT);
    int oc = rm/C_FEAT, ic = rm%C_FEAT;
    float v = w[(size_t)oc*4608 + ic*9 + r];
    __nv_bfloat16 h = __float2bfloat16(v);
    g_wcv_hi[idx]=h; g_wcv_lo[idx]=__float2bfloat16(v-__bfloat162float(h));
}

__global__ void k_zero(){
    int i = blockIdx.x*blockDim.x + threadIdx.x;
    if (i < M_BOXES*OCONV) g_zsum[i]=0.f;
}

// ---------------- FC1 HMMA GEMM: grid (8 n, 4 m, 8 splitK), 2-stage (R9) ----------------
__global__ void __launch_bounds__(256,2) k_mm1(){
    extern __shared__ __align__(16) char dynsm[];
    uint32_t sbase = smem_u32(dynsm);
    int tid = threadIdx.x, wid = tid>>5, L = tid&31;
    int widm = wid&3, widn = wid>>2;
    int bn = blockIdx.x, bm = blockIdx.y, sk = blockIdx.z;
    int rw = tid>>1, t1 = tid&1;
    int k0b = sk*KSLICE;
    const int nIter = KSLICE/32;   // 392

    const __nv_bfloat16* Asrc = (t1 ? g_pA_lo  : g_pA_hi)  + (size_t)(bm*128+rw)*KFC;
    const __nv_bfloat16* Bsrc = (t1 ? g_wfc_lo : g_wfc_hi) + (size_t)(bn*128+rw)*KFC;
    uint32_t ld_a = sbase + rw*PITCH + t1*64;
    uint32_t ld_b = ld_a + OPBYTES;

    uint32_t aA = sbase + (widm*32 + (L&7) + 8*((L>>3)&1))*PITCH + (L>>4)*16;
    uint32_t aB = sbase + OPBYTES + (widn*64 + (L&7) + 8*(L>>4))*PITCH + ((L>>3)&1)*16;

    float acc[16][4];
    #pragma unroll
    for (int i=0;i<16;i++){ acc[i][0]=0.f; acc[i][1]=0.f; acc[i][2]=0.f; acc[i][3]=0.f; }

#define FC_LD(ST,IT) do { \
        int kb_ = k0b + (IT)*32; \
        uint32_t off_ = (ST)*STAGEB; \
        _Pragma("unroll") \
        for (int j=0;j<4;j++) cp16(ld_a + off_ + j*16, Asrc + kb_ + j*8); \
        _Pragma("unroll") \
        for (int j=0;j<4;j++) cp16(ld_b + off_ + j*16, Bsrc + kb_ + j*8); \
        cp_commit(); } while(0)

    FC_LD(0,0);
    for (int it=0; it<nIter; ++it){
        if (it+1 < nIter){ FC_LD((it+1)&1, it+1); cp_wait<1>(); }
        else cp_wait<0>();
        __syncthreads();
        uint32_t off = (it&1)*STAGEB;
        hmma_tile(aA + off, aB + off, acc);
        __syncthreads();
    }
#undef FC_LD

    #pragma unroll
    for (int mi=0;mi<2;mi++)
        #pragma unroll
        for (int ni=0;ni<8;ni++)
            #pragma unroll
            for (int cq=0;cq<4;cq++){
                int row = bm*128 + widm*32 + mi*16 + (L>>2) + 8*(cq>>1);
                int col = bn*128 + widn*64 + ni*8 + 2*(L&3) + (cq&1);
                g_partial[((size_t)sk*M_BOXES + row)*HID + col] = acc[mi*8+ni][cq];
            }
}

__global__ void k_reduce1(const float* __restrict__ bfc1){
    int idx = blockIdx.x*blockDim.x + threadIdx.x;
    if (idx >= M_BOXES*HID) return;
    float v = 0.f;
    #pragma unroll
    for (int s=0;s<SPLITK;s++) v += g_partial[(size_t)s*M_BOXES*HID + idx];
    g_h[idx] = fmaxf(v + bfc1[idx%HID], 0.f);
}

__global__ void __launch_bounds__(128) k_heads(const float* __restrict__ wc, const float* __restrict__ bc,
                                               const float* __restrict__ wb, const float* __restrict__ bb,
                                               float* __restrict__ out){
    __shared__ float hrow[HID];
    __shared__ float lg[NCLS];
    __shared__ float mx, sm;
    int m = blockIdx.x, tid = threadIdx.x;
    for (int k=tid;k<HID;k+=blockDim.x) hrow[k] = g_h[m*HID+k];
    __syncthreads();
    if (tid<NCLS){
        float ac = bc[tid], ab = bb[tid];
        for (int k=0;k<HID;k++){
            float h = hrow[k];
            ac = fmaf(h, wc[k*NCLS+tid], ac);
            ab = fmaf(h, wb[k*NCLS+tid], ab);
        }
        lg[tid]=ac;
        out[PART + m*NCLS + tid] = ab;
    }
    __syncthreads();
    if (tid==0){ float v=-1e30f; for(int c=0;c<NCLS;c++) v=fmaxf(v,lg[c]); mx=v; }
    __syncthreads();
    if (tid<NCLS) lg[tid] = expf(lg[tid]-mx);
    __syncthreads();
    if (tid==0){ float v=0.f; for(int c=0;c<NCLS;c++) v+=lg[c]; sm=v; }
    __syncthreads();
    if (tid<NCLS) out[m*NCLS+tid] = lg[tid]/sm;
}

// ---------------- conv HMMA: 9 shifted taps in K; grid (2 n, 784 m), 2-stage (R9) ----------------
__global__ void __launch_bounds__(256,2) k_mm2(const float* __restrict__ bconv){
    extern __shared__ __align__(16) char dynsm[];
    uint32_t sbase = smem_u32(dynsm);
    int tid = threadIdx.x, wid = tid>>5, L = tid&31;
    int widm = wid&3, widn = wid>>2;
    int nbase = blockIdx.x*128;
    int rowbase = blockIdx.y*128;
    int rw = tid>>1, t1 = tid&1;
    const int nIter = 144;  // 9 taps * 16

    int grow = rowbase + rw;
    int am = grow/SP;
    int asp = grow - am*SP;
    int ay = asp/POOLSZ, ax = asp - ay*POOLSZ;
    const __nv_bfloat16* Abase0 = (t1 ? g_pA_lo : g_pA_hi) + (size_t)am*SP*C_FEAT;
    const __nv_bfloat16* Bsrc0  = (t1 ? g_wcv_lo : g_wcv_hi);
    uint32_t ld_a = sbase + rw*PITCH + t1*64;
    uint32_t ld_b = ld_a + OPBYTES;

    uint32_t aA = sbase + (widm*32 + (L&7) + 8*((L>>3)&1))*PITCH + (L>>4)*16;
    uint32_t aB = sbase + OPBYTES + (widn*64 + (L&7) + 8*(L>>4))*PITCH + ((L>>3)&1)*16;

    float acc[16][4];
    #pragma unroll
    for (int i=0;i<16;i++){ acc[i][0]=0.f; acc[i][1]=0.f; acc[i][2]=0.f; acc[i][3]=0.f; }

#define CV_LD(ST,IT) do { \
        int r_ = (IT)>>4, kk_ = ((IT)&15)*32; \
        int dy_ = r_/3 - 1, dx_ = r_ - (r_/3)*3 - 1; \
        int yy_ = ay+dy_, xx_ = ax+dx_; \
        int ok_ = (((unsigned)yy_ < (unsigned)POOLSZ) && ((unsigned)xx_ < (unsigned)POOLSZ)) ? 16 : 0; \
        const __nv_bfloat16* as_ = Abase0 + (size_t)(ok_ ? (yy_*POOLSZ+xx_) : 0)*C_FEAT + kk_; \
        const __nv_bfloat16* bs_ = Bsrc0 + ((size_t)r_*OCONV + nbase + rw)*C_FEAT + kk_; \
        uint32_t off_ = (ST)*STAGEB; \
        _Pragma("unroll") \
        for (int j=0;j<4;j++) cp16z(ld_a + off_ + j*16, as_ + j*8, ok_); \
        _Pragma("unroll") \
        for (int j=0;j<4;j++) cp16(ld_b + off_ + j*16, bs_ + j*8); \
        cp_commit(); } while(0)

    CV_LD(0,0);
    for (int it=0; it<nIter; ++it){
        if (it+1 < nIter){ CV_LD((it+1)&1, it+1); cp_wait<1>(); }
        else cp_wait<0>();
        __syncthreads();
        uint32_t off = (it&1)*STAGEB;
        hmma_tile(aA + off, aB + off, acc);
        __syncthreads();
    }
#undef CV_LD

    // epilogue: bias+relu, xor-shuffle reduce 8 rows, atomicAdd per box
    #pragma unroll
    for (int mi=0;mi<2;mi++)
        #pragma unroll
        for (int cq2=0;cq2<2;cq2++){
            int rbase = rowbase + widm*32 + mi*16 + 8*cq2;
            int b0 = rbase/SP, b1 = (rbase+7)/SP;
            int mybox = (rbase + (L>>2))/SP;
            #pragma unroll
            for (int ni=0;ni<8;ni++)
                #pragma unroll
                for (int q=0;q<2;q++){
                    int cq = cq2*2 + q;
                    int col = nbase + widn*64 + ni*8 + 2*(L&3) + q;
                    float z = fmaxf(acc[mi*8+ni][cq] + __ldg(&bconv[col]), 0.f);
                    float z0 = (mybox==b0) ? z : 0.f;
                    z0 += __shfl_xor_sync(0xffffffffu, z0, 4);
                    z0 += __shfl_xor_sync(0xffffffffu, z0, 8);
                    z0 += __shfl_xor_sync(0xffffffffu, z0, 16);
                    if ((L>>2)==0) atomicAdd(&g_zsum[b0*OCONV+col], z0);
                    if (b1 != b0){
                        float z1 = (mybox==b1) ? z : 0.f;
                        z1 += __shfl_xor_sync(0xffffffffu, z1, 4);
                        z1 += __shfl_xor_sync(0xffffffffu, z1, 8);
                        z1 += __shfl_xor_sync(0xffffffffu, z1, 16);
                        if ((L>>2)==0) atomicAdd(&g_zsum[b1*OCONV+col], z1);
                    }
                }
        }
}

__global__ void __launch_bounds__(128) k_maskhead(const float* __restrict__ wm,
                                                  const float* __restrict__ bm_,
                                                  float* __restrict__ out){
    int m = blockIdx.x, t = threadIdx.x;
    if (t >= NCLS) return;
    float acc = bm_[t];
    for (int oc=0; oc<OCONV; oc++)
        acc = fmaf(g_zsum[m*OCONV+oc]*(1.0f/196.0f), wm[oc*NCLS+t], acc);
    out[2*PART + m*NCLS + t] = 1.0f/(1.0f + expf(-acc));
}

extern "C" void kernel_launch(void* const* d_in, const int* in_sizes, int n_in,
                              void* d_out, int out_size){
    const float* p2     = (const float*)d_in[0];
    const float* p3     = (const float*)d_in[1];
    const float* p4     = (const float*)d_in[2];
    const float* p5     = (const float*)d_in[3];
    const float* boxes  = (const float*)d_in[4];
    const int*   bidx   = (const int*)  d_in[5];
    const float* w_fc1  = (const float*)d_in[6];
    const float* b_fc1  = (const float*)d_in[7];
    const float* w_cls  = (const float*)d_in[8];
    const float* b_cls  = (const float*)d_in[9];
    const float* w_box  = (const float*)d_in[10];
    const float* b_box  = (const float*)d_in[11];
    const float* w_conv = (const float*)d_in[12];
    const float* b_conv = (const float*)d_in[13];
    const float* w_mfc  = (const float*)d_in[14];
    const float* b_mfc  = (const float*)d_in[15];
    const int*   img_h  = (const int*)  d_in[16];
    const int*   img_w  = (const int*)  d_in[17];
    float* out = (float*)d_out;

    cudaFuncSetAttribute(k_mm1, cudaFuncAttributeMaxDynamicSharedMemorySize, 2*STAGEB);
    cudaFuncSetAttribute(k_mm2, cudaFuncAttributeMaxDynamicSharedMemorySize, 2*STAGEB);

    k_prep<<<1, 512>>>(boxes, bidx, img_h, img_w);
    k_wcvt<<<(9*OCONV*C_FEAT + 255)/256, 256>>>(w_conv);
    k_zero<<<(M_BOXES*OCONV + 255)/256, 256>>>();

    k_roi2<<<dim3(M_BOXES, C_FEAT/64), 256>>>(p2, p3, p4, p5);
    k_wfct<<<dim3(32, 16, 196), dim3(32, 8)>>>(w_fc1);

    k_mm1<<<dim3(8, 4, 8), 256, 2*STAGEB>>>();
    k_reduce1<<<(M_BOXES*HID + 255)/256, 256>>>(b_fc1);
    k_heads<<<M_BOXES, 128>>>(w_cls, b_cls, w_box, b_box, out);

    k_mm2<<<dim3(2, 784), 256, 2*STAGEB>>>(b_conv);
    k_maskhead<<<M_BOXES, 128>>>(w_mfc, b_mfc, out);
}

// round 15
// speedup vs baseline: 1.2978x; 1.0505x over previous
#include <cuda_runtime.h>
#include <cuda_bf16.h>
#include <math.h>
#include <stdint.h>

#define M_BOXES 512
#define C_FEAT  512
#define POOLSZ  14
#define SP      196
#define HID     1024
#define NCLS    81
#define OCONV   256
#define KFC     100352
#define SPLITK  8
#define KSLICE  (KFC/SPLITK)
#define PART    (M_BOXES*NCLS)
#define MROWS   (M_BOXES*SP)

// smem tile geometry: 128 rows x 8 chunks(16B) data + 1 pad chunk = 144B pitch
#define PITCH   144
#define OPBYTES (128*PITCH)      // 18432 per operand
#define STAGEB  (2*OPBYTES)      // 36864 per stage (A+B)

__device__ __nv_bfloat16 g_pA_hi[(size_t)MROWS*C_FEAT];
__device__ __nv_bfloat16 g_pA_lo[(size_t)MROWS*C_FEAT];
__device__ __nv_bfloat16 g_wfc_hi[(size_t)HID*KFC];
__device__ __nv_bfloat16 g_wfc_lo[(size_t)HID*KFC];
__device__ __nv_bfloat16 g_wcv_hi[(size_t)9*OCONV*C_FEAT];
__device__ __nv_bfloat16 g_wcv_lo[(size_t)9*OCONV*C_FEAT];
__device__ float         g_partial[(size_t)SPLITK*M_BOXES*HID];
__device__ float         g_h[M_BOXES*HID];
__device__ float         g_zsum[M_BOXES*OCONV];
__device__ float         g_boxp[M_BOXES*8];

__device__ __forceinline__ uint32_t smem_u32(const void* p){
    uint32_t a; asm("{ .reg .u64 t; cvta.to.shared.u64 t, %1; cvt.u32.u64 %0, t; }":"=r"(a):"l"(p)); return a;
}
__device__ __forceinline__ void cp16(uint32_t dst, const void* src){
    asm volatile("cp.async.ca.shared.global [%0], [%1], 16;"::"r"(dst),"l"(src));
}
__device__ __forceinline__ void cp16z(uint32_t dst, const void* src, int sz){
    asm volatile("cp.async.ca.shared.global [%0], [%1], 16, %2;"::"r"(dst),"l"(src),"r"(sz));
}
__device__ __forceinline__ void cp_commit(){ asm volatile("cp.async.commit_group;":::"memory"); }
template<int N> __device__ __forceinline__ void cp_wait(){
    asm volatile("cp.async.wait_group %0;"::"n"(N):"memory");
}
__device__ __forceinline__ void ldm4(uint32_t* f, uint32_t addr){
    asm volatile("ldmatrix.sync.aligned.m8n8.x4.shared.b16 {%0,%1,%2,%3}, [%4];"
        :"=r"(f[0]),"=r"(f[1]),"=r"(f[2]),"=r"(f[3]):"r"(addr));
}
__device__ __forceinline__ void mma16816(float* c, const uint32_t* a, const uint32_t* b){
    asm volatile("mma.sync.aligned.m16n8k16.row.col.f32.bf16.bf16.f32 "
        "{%0,%1,%2,%3},{%4,%5,%6,%7},{%8,%9},{%0,%1,%2,%3};"
        :"+f"(c[0]),"+f"(c[1]),"+f"(c[2]),"+f"(c[3])
        :"r"(a[0]),"r"(a[1]),"r"(a[2]),"r"(a[3]),"r"(b[0]),"r"(b[1]));
}

// 3-pass HMMA (hh, lh, hl) with B-hi reuse and NO extra live registers:
// per k-half: A-hi+B-hi -> hh; A regs <- A-lo -> lh; B regs <- B-lo, A regs <- A-hi -> hl.
// 28 ldm4/iter vs 36 baseline; fragment regs identical to baseline (8 A + 16 B).
__device__ __forceinline__ void hmma_tile(uint32_t aAddr, uint32_t bAddr, float acc[16][4]){
    #pragma unroll
    for (int s=0; s<2; s++){
        uint32_t af[2][4], bf[4][4];
        // A-hi + B-hi
        ldm4(af[0], aAddr + s*32);
        ldm4(af[1], aAddr + 16*PITCH + s*32);
        #pragma unroll
        for (int p=0;p<4;p++) ldm4(bf[p], bAddr + p*16*PITCH + s*32);
        #pragma unroll
        for (int mi=0;mi<2;mi++)
            #pragma unroll
            for (int ni=0;ni<8;ni++)
                mma16816(acc[mi*8+ni], af[mi], &bf[ni>>1][(ni&1)*2]);
        // A-lo (overwrite A regs), B-hi still live -> lh
        ldm4(af[0], aAddr + 64 + s*32);
        ldm4(af[1], aAddr + 16*PITCH + 64 + s*32);
        #pragma unroll
        for (int mi=0;mi<2;mi++)
            #pragma unroll
            for (int ni=0;ni<8;ni++)
                mma16816(acc[mi*8+ni], af[mi], &bf[ni>>1][(ni&1)*2]);
        // B-lo (overwrite B regs) + reload A-hi -> hl
        #pragma unroll
        for (int p=0;p<4;p++) ldm4(bf[p], bAddr + p*16*PITCH + 64 + s*32);
        ldm4(af[0], aAddr + s*32);
        ldm4(af[1], aAddr + 16*PITCH + s*32);
        #pragma unroll
        for (int mi=0;mi<2;mi++)
            #pragma unroll
            for (int ni=0;ni<8;ni++)
                mma16816(acc[mi*8+ni], af[mi], &bf[ni>>1][(ni&1)*2]);
    }
}

__global__ void k_prep(const float* __restrict__ boxes, const int* __restrict__ bidx,
                       const int* __restrict__ ph, const int* __restrict__ pw){
    int m = threadIdx.x; if (m >= M_BOXES) return;
    int ih = ph[0], iw = pw[0];
    if (ih <= 0 || ih > 100000) ih = (int)__int_as_float(ph[0]);
    if (iw <= 0 || iw > 100000) iw = (int)__int_as_float(pw[0]);
    float alpha = (224.0f/800.0f)*(float)min(ih,iw);
    float x1=boxes[m*4+0], y1=boxes[m*4+1], x2=boxes[m*4+2], y2=boxes[m*4+3];
    float s = sqrtf(fmaxf(fabsf(x2-x1)*fabsf(y2-y1), 1e-6f));
    float k = floorf(4.0f + log2f(s/alpha));
    int lvl = (int)fminf(fmaxf(k-2.0f,0.0f),3.0f);
    float sc = 1.0f/(float)(4<<lvl);
    g_boxp[m*8+0]=x1*sc; g_boxp[m*8+1]=y1*sc; g_boxp[m*8+2]=x2*sc; g_boxp[m*8+3]=y2*sc;
    g_boxp[m*8+4]=(float)lvl; g_boxp[m*8+5]=(float)bidx[m];
}

// fused RoIAlign + transpose + bf16 hi/lo split: block = (box m, 64-channel tile)
__global__ void __launch_bounds__(256) k_roi2(const float* __restrict__ p2, const float* __restrict__ p3,
                                              const float* __restrict__ p4, const float* __restrict__ p5){
    __shared__ float s[64][201];
    int m = blockIdx.x, c0 = blockIdx.y*64;
    const float* bp = &g_boxp[m*8];
    int lvl = (int)bp[4], bi = (int)bp[5];
    const float* feat = (lvl==0)?p2:(lvl==1)?p3:(lvl==2)?p4:p5;
    int H = 200>>lvl, W = H;
    float sx1 = bp[0], sy1 = bp[1], sx2 = bp[2], sy2 = bp[3];
    int tid = threadIdx.x;
    int cl = tid>>5, sps = tid&31;

    #pragma unroll
    for (int spc=0; spc<7; spc++){
        int sp = spc*32 + sps;
        if (sp < SP){
            int py = sp/POOLSZ, px = sp - py*POOLSZ;
            float xs = sx1 + (px+0.5f)/POOLSZ*(sx2-sx1);
            float ys = sy1 + (py+0.5f)/POOLSZ*(sy2-sy1);
            float x0f = floorf(xs), y0f = floorf(ys);
            float lx = xs-x0f, ly = ys-y0f;
            int ix0 = min(max((int)x0f,0),W-1), ix1 = min(max((int)x0f+1,0),W-1);
            int iy0 = min(max((int)y0f,0),H-1), iy1 = min(max((int)y0f+1,0),H-1);
            float w00 = (1.f-ly)*(1.f-lx), w01 = (1.f-ly)*lx, w10 = ly*(1.f-lx), w11 = ly*lx;
            int o00 = iy0*W+ix0, o01 = iy0*W+ix1, o10 = iy1*W+ix0, o11 = iy1*W+ix1;
            #pragma unroll
            for (int ci=0; ci<8; ci++){
                int c = c0 + cl*8 + ci;
                const float* base = feat + ((size_t)(bi*C_FEAT + c))*(size_t)(H*W);
                s[cl*8+ci][sp] = base[o00]*w00 + base[o01]*w01 + base[o10]*w10 + base[o11]*w11;
            }
        }
    }
    __syncthreads();
    int cl2 = tid&63, sp2 = tid>>6;
    #pragma unroll 7
    for (int j=0;j<49;j++){
        int sp = sp2 + j*4;
        float v = s[cl2][sp];
        __nv_bfloat16 h = __float2bfloat16(v);
        size_t o = ((size_t)m*SP+sp)*C_FEAT + c0 + cl2;
        g_pA_hi[o]=h; g_pA_lo[o]=__float2bfloat16(v-__bfloat162float(h));
    }
}

// w_fc1 [c*196+sp][n] -> [n][sp*512+c] hi/lo
__global__ void __launch_bounds__(256) k_wfct(const float* __restrict__ w){
    __shared__ float s[32][33];
    int sp = blockIdx.z, c0 = blockIdx.y*32, n0 = blockIdx.x*32;
    int tx = threadIdx.x, ty = threadIdx.y;
    #pragma unroll
    for (int i=0;i<4;i++){
        int cl = ty+i*8;
        s[cl][tx] = w[((size_t)(c0+cl)*SP+sp)*HID + n0+tx];
    }
    __syncthreads();
    #pragma unroll
    for (int i=0;i<4;i++){
        int nl = ty+i*8;
        float v = s[tx][nl];
        __nv_bfloat16 h = __float2bfloat16(v);
        size_t o = (size_t)(n0+nl)*KFC + (size_t)sp*C_FEAT + c0+tx;
        g_wfc_hi[o]=h; g_wfc_lo[o]=__float2bfloat16(v-__bfloat162float(h));
    }
}

// w_conv OIHW -> [r][oc][ic] hi/lo
__global__ void k_wcvt(const float* __restrict__ w){
    int idx = blockIdx.x*blockDim.x + threadIdx.x;
    if (idx >= 9*OCONV*C_FEAT) return;
    int r = idx/(OCONV*C_FEAT), rm = idx%(OCONV*C_FEAT);
    int oc = rm/C_FEAT, ic = rm%C_FEAT;
    float v = w[(size_t)oc*4608 + ic*9 + r];
    __nv_bfloat16 h = __float2bfloat16(v);
    g_wcv_hi[idx]=h; g_wcv_lo[idx]=__float2bfloat16(v-__bfloat162float(h));
}

__global__ void k_zero(){
    int i = blockIdx.x*blockDim.x + threadIdx.x;
    if (i < M_BOXES*OCONV) g_zsum[i]=0.f;
}

// ---------------- FC1 HMMA GEMM: grid (8 n, 4 m, 8 splitK), 2-stage ----------------
__global__ void __launch_bounds__(256,2) k_mm1(){
    extern __shared__ __align__(16) char dynsm[];
    uint32_t sbase = smem_u32(dynsm);
    int tid = threadIdx.x, wid = tid>>5, L = tid&31;
    int widm = wid&3, widn = wid>>2;
    int bn = blockIdx.x, bm = blockIdx.y, sk = blockIdx.z;
    int rw = tid>>1, t1 = tid&1;
    int k0b = sk*KSLICE;
    const int nIter = KSLICE/32;   // 392

    const __nv_bfloat16* Asrc = (t1 ? g_pA_lo  : g_pA_hi)  + (size_t)(bm*128+rw)*KFC;
    const __nv_bfloat16* Bsrc = (t1 ? g_wfc_lo : g_wfc_hi) + (size_t)(bn*128+rw)*KFC;
    uint32_t ld_a = sbase + rw*PITCH + t1*64;
    uint32_t ld_b = ld_a + OPBYTES;

    uint32_t aA = sbase + (widm*32 + (L&7) + 8*((L>>3)&1))*PITCH + (L>>4)*16;
    uint32_t aB = sbase + OPBYTES + (widn*64 + (L&7) + 8*(L>>4))*PITCH + ((L>>3)&1)*16;

    float acc[16][4];
    #pragma unroll
    for (int i=0;i<16;i++){ acc[i][0]=0.f; acc[i][1]=0.f; acc[i][2]=0.f; acc[i][3]=0.f; }

#define FC_LD(ST,IT) do { \
        int kb_ = k0b + (IT)*32; \
        uint32_t off_ = (ST)*STAGEB; \
        _Pragma("unroll") \
        for (int j=0;j<4;j++) cp16(ld_a + off_ + j*16, Asrc + kb_ + j*8); \
        _Pragma("unroll") \
        for (int j=0;j<4;j++) cp16(ld_b + off_ + j*16, Bsrc + kb_ + j*8); \
        cp_commit(); } while(0)

    FC_LD(0,0);
    for (int it=0; it<nIter; ++it){
        if (it+1 < nIter){ FC_LD((it+1)&1, it+1); cp_wait<1>(); }
        else cp_wait<0>();
        __syncthreads();
        uint32_t off = (it&1)*STAGEB;
        hmma_tile(aA + off, aB + off, acc);
        __syncthreads();
    }
#undef FC_LD

    #pragma unroll
    for (int mi=0;mi<2;mi++)
        #pragma unroll
        for (int ni=0;ni<8;ni++)
            #pragma unroll
            for (int cq=0;cq<4;cq++){
                int row = bm*128 + widm*32 + mi*16 + (L>>2) + 8*(cq>>1);
                int col = bn*128 + widn*64 + ni*8 + 2*(L&3) + (cq&1);
                g_partial[((size_t)sk*M_BOXES + row)*HID + col] = acc[mi*8+ni][cq];
            }
}

__global__ void k_reduce1(const float* __restrict__ bfc1){
    int idx = blockIdx.x*blockDim.x + threadIdx.x;
    if (idx >= M_BOXES*HID) return;
    float v = 0.f;
    #pragma unroll
    for (int s=0;s<SPLITK;s++) v += g_partial[(size_t)s*M_BOXES*HID + idx];
    g_h[idx] = fmaxf(v + bfc1[idx%HID], 0.f);
}

__global__ void __launch_bounds__(128) k_heads(const float* __restrict__ wc, const float* __restrict__ bc,
                                               const float* __restrict__ wb, const float* __restrict__ bb,
                                               float* __restrict__ out){
    __shared__ float hrow[HID];
    __shared__ float lg[NCLS];
    __shared__ float mx, sm;
    int m = blockIdx.x, tid = threadIdx.x;
    for (int k=tid;k<HID;k+=blockDim.x) hrow[k] = g_h[m*HID+k];
    __syncthreads();
    if (tid<NCLS){
        float ac = bc[tid], ab = bb[tid];
        for (int k=0;k<HID;k++){
            float h = hrow[k];
            ac = fmaf(h, wc[k*NCLS+tid], ac);
            ab = fmaf(h, wb[k*NCLS+tid], ab);
        }
        lg[tid]=ac;
        out[PART + m*NCLS + tid] = ab;
    }
    __syncthreads();
    if (tid==0){ float v=-1e30f; for(int c=0;c<NCLS;c++) v=fmaxf(v,lg[c]); mx=v; }
    __syncthreads();
    if (tid<NCLS) lg[tid] = expf(lg[tid]-mx);
    __syncthreads();
    if (tid==0){ float v=0.f; for(int c=0;c<NCLS;c++) v+=lg[c]; sm=v; }
    __syncthreads();
    if (tid<NCLS) out[m*NCLS+tid] = lg[tid]/sm;
}

// ---------------- conv HMMA: 9 shifted taps in K; grid (2 n, 784 m), 2-stage ----------------
__global__ void __launch_bounds__(256,2) k_mm2(const float* __restrict__ bconv){
    extern __shared__ __align__(16) char dynsm[];
    uint32_t sbase = smem_u32(dynsm);
    int tid = threadIdx.x, wid = tid>>5, L = tid&31;
    int widm = wid&3, widn = wid>>2;
    int nbase = blockIdx.x*128;
    int rowbase = blockIdx.y*128;
    int rw = tid>>1, t1 = tid&1;
    const int nIter = 144;  // 9 taps * 16

    int grow = rowbase + rw;
    int am = grow/SP;
    int asp = grow - am*SP;
    int ay = asp/POOLSZ, ax = asp - ay*POOLSZ;
    const __nv_bfloat16* Abase0 = (t1 ? g_pA_lo : g_pA_hi) + (size_t)am*SP*C_FEAT;
    const __nv_bfloat16* Bsrc0  = (t1 ? g_wcv_lo : g_wcv_hi);
    uint32_t ld_a = sbase + rw*PITCH + t1*64;
    uint32_t ld_b = ld_a + OPBYTES;

    uint32_t aA = sbase + (widm*32 + (L&7) + 8*((L>>3)&1))*PITCH + (L>>4)*16;
    uint32_t aB = sbase + OPBYTES + (widn*64 + (L&7) + 8*(L>>4))*PITCH + ((L>>3)&1)*16;

    float acc[16][4];
    #pragma unroll
    for (int i=0;i<16;i++){ acc[i][0]=0.f; acc[i][1]=0.f; acc[i][2]=0.f; acc[i][3]=0.f; }

#define CV_LD(ST,IT) do { \
        int r_ = (IT)>>4, kk_ = ((IT)&15)*32; \
        int dy_ = r_/3 - 1, dx_ = r_ - (r_/3)*3 - 1; \
        int yy_ = ay+dy_, xx_ = ax+dx_; \
        int ok_ = (((unsigned)yy_ < (unsigned)POOLSZ) && ((unsigned)xx_ < (unsigned)POOLSZ)) ? 16 : 0; \
        const __nv_bfloat16* as_ = Abase0 + (size_t)(ok_ ? (yy_*POOLSZ+xx_) : 0)*C_FEAT + kk_; \
        const __nv_bfloat16* bs_ = Bsrc0 + ((size_t)r_*OCONV + nbase + rw)*C_FEAT + kk_; \
        uint32_t off_ = (ST)*STAGEB; \
        _Pragma("unroll") \
        for (int j=0;j<4;j++) cp16z(ld_a + off_ + j*16, as_ + j*8, ok_); \
        _Pragma("unroll") \
        for (int j=0;j<4;j++) cp16(ld_b + off_ + j*16, bs_ + j*8); \
        cp_commit(); } while(0)

    CV_LD(0,0);
    for (int it=0; it<nIter; ++it){
        if (it+1 < nIter){ CV_LD((it+1)&1, it+1); cp_wait<1>(); }
        else cp_wait<0>();
        __syncthreads();
        uint32_t off = (it&1)*STAGEB;
        hmma_tile(aA + off, aB + off, acc);
        __syncthreads();
    }
#undef CV_LD

    // epilogue: bias+relu, xor-shuffle reduce 8 rows, atomicAdd per box
    #pragma unroll
    for (int mi=0;mi<2;mi++)
        #pragma unroll
        for (int cq2=0;cq2<2;cq2++){
            int rbase = rowbase + widm*32 + mi*16 + 8*cq2;
            int b0 = rbase/SP, b1 = (rbase+7)/SP;
            int mybox = (rbase + (L>>2))/SP;
            #pragma unroll
            for (int ni=0;ni<8;ni++)
                #pragma unroll
                for (int q=0;q<2;q++){
                    int cq = cq2*2 + q;
                    int col = nbase + widn*64 + ni*8 + 2*(L&3) + q;
                    float z = fmaxf(acc[mi*8+ni][cq] + __ldg(&bconv[col]), 0.f);
                    float z0 = (mybox==b0) ? z : 0.f;
                    z0 += __shfl_xor_sync(0xffffffffu, z0, 4);
                    z0 += __shfl_xor_sync(0xffffffffu, z0, 8);
                    z0 += __shfl_xor_sync(0xffffffffu, z0, 16);
                    if ((L>>2)==0) atomicAdd(&g_zsum[b0*OCONV+col], z0);
                    if (b1 != b0){
                        float z1 = (mybox==b1) ? z : 0.f;
                        z1 += __shfl_xor_sync(0xffffffffu, z1, 4);
                        z1 += __shfl_xor_sync(0xffffffffu, z1, 8);
                        z1 += __shfl_xor_sync(0xffffffffu, z1, 16);
                        if ((L>>2)==0) atomicAdd(&g_zsum[b1*OCONV+col], z1);
                    }
                }
        }
}

__global__ void __launch_bounds__(128) k_maskhead(const float* __restrict__ wm,
                                                  const float* __restrict__ bm_,
                                                  float* __restrict__ out){
    int m = blockIdx.x, t = threadIdx.x;
    if (t >= NCLS) return;
    float acc = bm_[t];
    for (int oc=0; oc<OCONV; oc++)
        acc = fmaf(g_zsum[m*OCONV+oc]*(1.0f/196.0f), wm[oc*NCLS+t], acc);
    out[2*PART + m*NCLS + t] = 1.0f/(1.0f + expf(-acc));
}

extern "C" void kernel_launch(void* const* d_in, const int* in_sizes, int n_in,
                              void* d_out, int out_size){
    const float* p2     = (const float*)d_in[0];
    const float* p3     = (const float*)d_in[1];
    const float* p4     = (const float*)d_in[2];
    const float* p5     = (const float*)d_in[3];
    const float* boxes  = (const float*)d_in[4];
    const int*   bidx   = (const int*)  d_in[5];
    const float* w_fc1  = (const float*)d_in[6];
    const float* b_fc1  = (const float*)d_in[7];
    const float* w_cls  = (const float*)d_in[8];
    const float* b_cls  = (const float*)d_in[9];
    const float* w_box  = (const float*)d_in[10];
    const float* b_box  = (const float*)d_in[11];
    const float* w_conv = (const float*)d_in[12];
    const float* b_conv = (const float*)d_in[13];
    const float* w_mfc  = (const float*)d_in[14];
    const float* b_mfc  = (const float*)d_in[15];
    const int*   img_h  = (const int*)  d_in[16];
    const int*   img_w  = (const int*)  d_in[17];
    float* out = (float*)d_out;

    cudaFuncSetAttribute(k_mm1, cudaFuncAttributeMaxDynamicSharedMemorySize, 2*STAGEB);
    cudaFuncSetAttribute(k_mm2, cudaFuncAttributeMaxDynamicSharedMemorySize, 2*STAGEB);

    k_prep<<<1, 512>>>(boxes, bidx, img_h, img_w);
    k_wcvt<<<(9*OCONV*C_FEAT + 255)/256, 256>>>(w_conv);
    k_zero<<<(M_BOXES*OCONV + 255)/256, 256>>>();

    k_roi2<<<dim3(M_BOXES, C_FEAT/64), 256>>>(p2, p3, p4, p5);
    k_wfct<<<dim3(32, 16, 196), dim3(32, 8)>>>(w_fc1);

    k_mm1<<<dim3(8, 4, 8), 256, 2*STAGEB>>>();
    k_reduce1<<<(M_BOXES*HID + 255)/256, 256>>>(b_fc1);
    k_heads<<<M_BOXES, 128>>>(w_cls, b_cls, w_box, b_box, out);

    k_mm2<<<dim3(2, 784), 256, 2*STAGEB>>>(b_conv);
    k_maskhead<<<M_BOXES, 128>>>(w_mfc, b_mfc, out);
}